// round 4
// baseline (speedup 1.0000x reference)
#include <cuda_runtime.h>
#include <cuda_bf16.h>
#include <cstdint>
#include <math.h>

#define BATCH 16
#define CIN   64
#define LEN   1024
#define HID   1024
#define OUTC  512
#define EPS   1e-5f
#define MTOT  (BATCH*LEN)   // 16384

// GEMM tiling: CTA 128(M) x 256(N), KC=16 source-k per stage, 3-stage ring
#define KC     16
#define NK     (HID/KC)      // 64 stages
#define A_ST   24576         // 3 o-planes * 128 rows * 64B
#define B_ST   49152         // 3 o-planes * 256 rows * 64B
#define STG    (A_ST + B_ST) // 73728
#define NSTG   3
#define SMEM_GEMM (NSTG*STG) // 221184

// fp32 SIMT proj tile params
#define GBM 128
#define GBN 128
#define GBK 16
#define GTM 8
#define GTN 8
#define NTHR 256

// ---------------- scratch ----------------
__device__ __align__(16)  float g_h0[MTOT*HID];
__device__ __align__(16)  float g_h1[MTOT*HID];
__device__ __align__(16)  float g_h2[MTOT*OUTC];
__device__ __align__(128) __nv_bfloat16 g_A6a[(size_t)MTOT*6144];   // [m][plane][k]
__device__ __align__(128) __nv_bfloat16 g_A6b[(size_t)MTOT*6144];
__device__ __align__(128) __nv_bfloat16 g_B6a[(size_t)6*HID*1024];  // [plane][n][k]
__device__ __align__(128) __nv_bfloat16 g_B6b[(size_t)6*OUTC*1024];
__device__ float g_c01[HID];
__device__ float g_c02[OUTC];

// ---------------- helpers ----------------
__device__ __forceinline__ uint32_t smem_u32(const void* p) {
    uint32_t a;
    asm("{ .reg .u64 t; cvta.to.shared.u64 t, %1; cvt.u32.u64 %0, t; }" : "=r"(a) : "l"(p));
    return a;
}

#define LDSM_X4(r, addr) \
    asm volatile("ldmatrix.sync.aligned.m8n8.x4.shared.b16 {%0,%1,%2,%3}, [%4];" \
        : "=r"((r)[0]), "=r"((r)[1]), "=r"((r)[2]), "=r"((r)[3]) : "r"(addr))
#define LDSM_X2(r, addr) \
    asm volatile("ldmatrix.sync.aligned.m8n8.x2.shared.b16 {%0,%1}, [%2];" \
        : "=r"((r)[0]), "=r"((r)[1]) : "r"(addr))
#define MMA16816(d, a, b) \
    asm volatile("mma.sync.aligned.m16n8k16.row.col.f32.bf16.bf16.f32 " \
        "{%0,%1,%2,%3}, {%4,%5,%6,%7}, {%8,%9}, {%0,%1,%2,%3};" \
        : "+f"((d)[0]), "+f"((d)[1]), "+f"((d)[2]), "+f"((d)[3]) \
        : "r"((a)[0]), "r"((a)[1]), "r"((a)[2]), "r"((a)[3]), "r"((b)[0]), "r"((b)[1]))

// ---------------- B repack + c0 ----------------
template<int STAGE>
__global__ void repackB_kernel(const float* __restrict__ coeffs, const float* __restrict__ bias) {
    const int N = (STAGE == 1) ? HID : OUTC;
    __nv_bfloat16* B6 = (STAGE == 1) ? g_B6a : g_B6b;
    float* c0         = (STAGE == 1) ? g_c01 : g_c02;
    int o = blockIdx.x;
    __shared__ float red[256];
    float s = 0.f;
    #pragma unroll
    for (int it = 0; it < 4; it++) {
        int c = threadIdx.x + it * 256;
        float4 v = *reinterpret_cast<const float4*>(coeffs + ((size_t)o * HID + c) * 4);
        s += v.x;
        size_t base = (size_t)o * 1024 + c;
        size_t ps = (size_t)N * 1024;
        __nv_bfloat16 h;
        h = __float2bfloat16(v.y); B6[0*ps + base] = h; B6[1*ps + base] = __float2bfloat16(v.y - __bfloat162float(h));
        h = __float2bfloat16(v.z); B6[2*ps + base] = h; B6[3*ps + base] = __float2bfloat16(v.z - __bfloat162float(h));
        h = __float2bfloat16(v.w); B6[4*ps + base] = h; B6[5*ps + base] = __float2bfloat16(v.w - __bfloat162float(h));
    }
    red[threadIdx.x] = s; __syncthreads();
    #pragma unroll
    for (int st = 128; st > 0; st >>= 1) {
        if (threadIdx.x < st) red[threadIdx.x] += red[threadIdx.x + st];
        __syncthreads();
    }
    if (threadIdx.x == 0) c0[o] = red[0] + bias[o];
}

// ---------------- projection GEMM (fp32 SIMT; tiny) ----------------
__global__ void gemm_proj_kernel(const float* __restrict__ x, const float* __restrict__ W,
                                 const float* __restrict__ bias) {
    __shared__ float As[GBK][GBM];
    __shared__ float Bs[GBK][GBN];
    const int m0 = blockIdx.y * GBM, n0 = blockIdx.x * GBN;
    const int tid = threadIdx.x;
    const int tx = tid & 15, ty = tid >> 4;
    float acc[GTM][GTN] = {};
    for (int kt = 0; kt < CIN; kt += GBK) {
        #pragma unroll
        for (int ii = 0; ii < 8; ii++) {
            int idx = tid + ii * NTHR;
            int mm = idx & (GBM - 1);
            int kk = idx >> 7;
            int m = m0 + mm;
            As[kk][mm] = x[((size_t)(m >> 10) * CIN + (kt + kk)) * LEN + (m & 1023)];
        }
        #pragma unroll
        for (int ii = 0; ii < 8; ii++) {
            int idx = tid + ii * NTHR;
            int nn = idx & (GBN - 1);
            int kk = idx >> 7;
            Bs[kk][nn] = W[(size_t)(kt + kk) * HID + n0 + nn];
        }
        __syncthreads();
        #pragma unroll
        for (int kk = 0; kk < GBK; kk++) {
            float a[GTM], bb[GTN];
            #pragma unroll
            for (int i = 0; i < GTM; i++) a[i] = As[kk][ty * GTM + i];
            #pragma unroll
            for (int j = 0; j < GTN; j++) bb[j] = Bs[kk][tx * GTN + j];
            #pragma unroll
            for (int i = 0; i < GTM; i++)
                #pragma unroll
                for (int j = 0; j < GTN; j++)
                    acc[i][j] = fmaf(a[i], bb[j], acc[i][j]);
        }
        __syncthreads();
    }
    #pragma unroll
    for (int i = 0; i < GTM; i++) {
        int m = m0 + ty * GTM + i;
        float* Cp = g_h0 + (size_t)m * HID + n0 + tx * GTN;
        #pragma unroll
        for (int j = 0; j < GTN; j++) Cp[j] = acc[i][j] + bias[n0 + tx * GTN + j];
    }
}

// ---------------- split helpers (vectorized: 8 consecutive k per thread) ----------------
__device__ __forceinline__ void split_store8(__nv_bfloat16* dst, const float* v) {
    // dst points at A6[m][0][k8]; planes offset by 1024 elements
    __nv_bfloat162 h4[4], l4[4];
    #pragma unroll
    for (int q = 0; q < 4; q++) {
        float a = v[2*q], b = v[2*q+1];
        __nv_bfloat16 ha = __float2bfloat16(a), hb = __float2bfloat16(b);
        h4[q] = __nv_bfloat162(ha, hb);
        l4[q] = __nv_bfloat162(__float2bfloat16(a - __bfloat162float(ha)),
                               __float2bfloat16(b - __bfloat162float(hb)));
    }
    *reinterpret_cast<uint4*>(dst)        = *reinterpret_cast<uint4*>(h4);
    *reinterpret_cast<uint4*>(dst + 1024) = *reinterpret_cast<uint4*>(l4);
}

__global__ void splitA_kernel() {
    size_t gid = (size_t)blockIdx.x * 256 + threadIdx.x;   // MTOT*128 threads
    int m = (int)(gid >> 7);
    int k8 = (int)(gid & 127) * 8;
    const float* src = g_h0 + (size_t)m * HID + k8;
    float x1[8], x2[8], x3[8];
    #pragma unroll
    for (int q = 0; q < 2; q++) {
        float4 v = *reinterpret_cast<const float4*>(src + q * 4);
        float* xp = x1 + q * 4;
        xp[0] = v.x; xp[1] = v.y; xp[2] = v.z; xp[3] = v.w;
    }
    #pragma unroll
    for (int i = 0; i < 8; i++) { x2[i] = x1[i] * x1[i]; x3[i] = x2[i] * x1[i]; }
    __nv_bfloat16* dst = g_A6a + (size_t)m * 6144 + k8;
    split_store8(dst,        x1);
    split_store8(dst + 2048, x2);
    split_store8(dst + 4096, x3);
}

// ---------------- LN + exact GELU + split ----------------
__device__ __forceinline__ float block_reduce_sum(float v, float* red, int t) {
    red[t] = v; __syncthreads();
    #pragma unroll
    for (int st = 128; st > 0; st >>= 1) {
        if (t < st) red[t] += red[t + st];
        __syncthreads();
    }
    float r = red[0];
    __syncthreads();
    return r;
}

__global__ void ln_gelu_split_kernel(const float* __restrict__ g, const float* __restrict__ beta) {
    __shared__ float red[256];
    int t = threadIdx.x;
    const float* p = g_h1 + (size_t)blockIdx.x * HID;
    float4 v4 = *reinterpret_cast<const float4*>(p + t * 4);
    float v[4] = {v4.x, v4.y, v4.z, v4.w};
    float s = v[0] + v[1] + v[2] + v[3];
    float mu = block_reduce_sum(s, red, t) * (1.f / HID);
    float s2 = 0.f;
    #pragma unroll
    for (int i = 0; i < 4; i++) { float d = v[i] - mu; s2 += d * d; }
    float rstd = rsqrtf(block_reduce_sum(s2, red, t) * (1.f / HID) + EPS);
    const float4 gg = *reinterpret_cast<const float4*>(g + t * 4);
    const float4 bb = *reinterpret_cast<const float4*>(beta + t * 4);
    float y[4];
    y[0] = (v[0] - mu) * rstd * gg.x + bb.x;
    y[1] = (v[1] - mu) * rstd * gg.y + bb.y;
    y[2] = (v[2] - mu) * rstd * gg.z + bb.z;
    y[3] = (v[3] - mu) * rstd * gg.w + bb.w;
    __nv_bfloat16* Ap = g_A6b + (size_t)blockIdx.x * 6144 + t * 4;
    __nv_bfloat162 h2[2], l2[2];
    float p1[4], p2[4], p3[4];
    #pragma unroll
    for (int i = 0; i < 4; i++) {
        float yy = y[i];
        yy = 0.5f * yy * (1.f + erff(yy * 0.70710678118654752f));
        p1[i] = yy; p2[i] = yy * yy; p3[i] = p2[i] * yy;
    }
    #pragma unroll
    for (int o = 0; o < 3; o++) {
        const float* pp = (o == 0) ? p1 : (o == 1) ? p2 : p3;
        #pragma unroll
        for (int q = 0; q < 2; q++) {
            float a = pp[2*q], b = pp[2*q+1];
            __nv_bfloat16 ha = __float2bfloat16(a), hb = __float2bfloat16(b);
            h2[q] = __nv_bfloat162(ha, hb);
            l2[q] = __nv_bfloat162(__float2bfloat16(a - __bfloat162float(ha)),
                                   __float2bfloat16(b - __bfloat162float(hb)));
        }
        *reinterpret_cast<uint2*>(Ap + o * 2048)        = *reinterpret_cast<uint2*>(h2);
        *reinterpret_cast<uint2*>(Ap + o * 2048 + 1024) = *reinterpret_cast<uint2*>(l2);
    }
}

// ---------------- fused KAN GEMM via mma.sync ----------------
// smem row layout per row (64B): [h_k0(16B) | h_k1 | l_k0 | l_k1], chunk c = hl*2 + k16half
// swizzled: chunk' = c ^ ((row>>1)&3)
__device__ __forceinline__ void load_stage_kan(const __nv_bfloat16* A6, const __nv_bfloat16* B6,
                                               int N, int m0, int n0, int kt,
                                               uint32_t bufA, uint32_t bufB, int tid) {
    int k0 = kt * KC;
    #pragma unroll
    for (int i = 0; i < 6; i++) {            // A: 6 planes * 128 rows * 2 chunks = 1536
        int id = tid + i * 256;
        int c16 = id & 1;
        int m = (id >> 1) & 127;
        int pl = id >> 8;                    // 0..5
        int o = pl >> 1, hl = pl & 1;
        const void* gp = (const void*)(A6 + (size_t)(m0 + m) * 6144 + pl * 1024 + k0 + c16 * 8);
        uint32_t sp = bufA + o * 8192 + m * 64
                    + ((uint32_t)(((hl << 1) | c16) ^ ((m >> 1) & 3)) << 4);
        asm volatile("cp.async.cg.shared.global [%0], [%1], 16;" :: "r"(sp), "l"(gp));
    }
    #pragma unroll
    for (int i = 0; i < 12; i++) {           // B: 6 planes * 256 rows * 2 chunks = 3072
        int id = tid + i * 256;
        int c16 = id & 1;
        int n = (id >> 1) & 255;
        int pl = id >> 9;
        int o = pl >> 1, hl = pl & 1;
        const void* gp = (const void*)(B6 + (size_t)pl * N * 1024 + (size_t)(n0 + n) * 1024 + k0 + c16 * 8);
        uint32_t sp = bufB + o * 16384 + n * 64
                    + ((uint32_t)(((hl << 1) | c16) ^ ((n >> 1) & 3)) << 4);
        asm volatile("cp.async.cg.shared.global [%0], [%1], 16;" :: "r"(sp), "l"(gp));
    }
}

template<int STAGE>
__global__ void __launch_bounds__(256, 1) gemm_kan_mma() {
    const int N             = (STAGE == 1) ? HID : OUTC;
    const __nv_bfloat16* A6 = (STAGE == 1) ? g_A6a : g_A6b;
    const __nv_bfloat16* B6 = (STAGE == 1) ? g_B6a : g_B6b;
    const float* c0v        = (STAGE == 1) ? g_c01 : g_c02;
    float* C                = (STAGE == 1) ? g_h1 : g_h2;

    extern __shared__ char smem[];
    uint32_t sb = smem_u32(smem);
    int tid = threadIdx.x, lane = tid & 31, w = tid >> 5;
    int wm = w >> 2, wn = w & 3;              // warp grid 2(M) x 4(N); warp tile 64x64
    int m0 = blockIdx.y * 128, n0 = blockIdx.x * 256;

    float acc[4][8][4] = {};

    int hiA = lane >> 4;
    int hiB = (lane >> 3) & 1;
    uint32_t aOff[4]; int aSw[4];
    uint32_t bOff[8]; int bSw[8];
    #pragma unroll
    for (int s = 0; s < 4; s++) {
        int r = wm * 64 + s * 16 + (lane & 15);
        aOff[s] = (uint32_t)r * 64; aSw[s] = (r >> 1) & 3;
    }
    #pragma unroll
    for (int t = 0; t < 8; t++) {
        int r = wn * 64 + t * 8 + (lane & 7);
        bOff[t] = (uint32_t)r * 64; bSw[t] = (r >> 1) & 3;
    }

    // prologue: 3 stages
    #pragma unroll
    for (int s = 0; s < NSTG; s++) {
        load_stage_kan(A6, B6, N, m0, n0, s, sb + s * STG, sb + s * STG + A_ST, tid);
        asm volatile("cp.async.commit_group;" ::: "memory");
    }

    for (int kt = 0; kt < NK; kt++) {
        asm volatile("cp.async.wait_group 2;" ::: "memory");
        __syncthreads();
        uint32_t bufA = sb + (uint32_t)(kt % NSTG) * STG;
        uint32_t bufB = bufA + A_ST;

        #pragma unroll
        for (int o = 0; o < 3; o++) {
            uint32_t bh[8][2], bl[8][2];
            #pragma unroll
            for (int t = 0; t < 8; t++) {
                uint32_t base = bufB + o * 16384 + bOff[t];
                LDSM_X2(bh[t], base + ((uint32_t)(hiB       ^ bSw[t]) << 4));
                LDSM_X2(bl[t], base + ((uint32_t)((2 + hiB) ^ bSw[t]) << 4));
            }
            #pragma unroll
            for (int s = 0; s < 4; s++) {
                uint32_t ah[4], al[4];
                uint32_t base = bufA + o * 8192 + aOff[s];
                LDSM_X4(ah, base + ((uint32_t)(hiA       ^ aSw[s]) << 4));
                LDSM_X4(al, base + ((uint32_t)((2 + hiA) ^ aSw[s]) << 4));
                #pragma unroll
                for (int t = 0; t < 8; t++) {
                    MMA16816(acc[s][t], ah, bh[t]);
                    MMA16816(acc[s][t], al, bh[t]);
                    MMA16816(acc[s][t], ah, bl[t]);
                }
            }
        }
        __syncthreads();
        int j = kt + NSTG;
        if (j < NK)
            load_stage_kan(A6, B6, N, m0, n0, j, bufA, bufB, tid);
        asm volatile("cp.async.commit_group;" ::: "memory");
    }

    // epilogue
    #pragma unroll
    for (int t = 0; t < 8; t++) {
        int col = n0 + wn * 64 + t * 8 + (lane & 3) * 2;
        float c0a = c0v[col], c0b = c0v[col + 1];
        #pragma unroll
        for (int s = 0; s < 4; s++) {
            int r0 = m0 + wm * 64 + s * 16 + (lane >> 2);
            float2 v0 = make_float2(acc[s][t][0] + c0a, acc[s][t][1] + c0b);
            float2 v1 = make_float2(acc[s][t][2] + c0a, acc[s][t][3] + c0b);
            *reinterpret_cast<float2*>(C + (size_t)r0 * N + col) = v0;
            *reinterpret_cast<float2*>(C + (size_t)(r0 + 8) * N + col) = v1;
        }
    }
}

// ---------------- LayerNorm 2 ----------------
__global__ void ln2_kernel(const float* __restrict__ g, const float* __restrict__ beta) {
    __shared__ float red[256];
    int t = threadIdx.x;
    float* p = g_h2 + (size_t)blockIdx.x * OUTC;
    float v[2];
    float s = 0.f;
    #pragma unroll
    for (int i = 0; i < 2; i++) { v[i] = p[t + i * 256]; s += v[i]; }
    float mu = block_reduce_sum(s, red, t) * (1.f / OUTC);
    float s2 = 0.f;
    #pragma unroll
    for (int i = 0; i < 2; i++) { float d = v[i] - mu; s2 += d * d; }
    float rstd = rsqrtf(block_reduce_sum(s2, red, t) * (1.f / OUTC) + EPS);
    #pragma unroll
    for (int i = 0; i < 2; i++) {
        int o = t + i * 256;
        p[o] = (v[i] - mu) * rstd * g[o] + beta[o];
    }
}

// ---------------- mean over L ----------------
__global__ void reduce_kernel(float* __restrict__ out) {
    int b = blockIdx.x, o = threadIdx.x;
    const float* p = g_h2 + (size_t)b * LEN * OUTC + o;
    float s = 0.f;
    #pragma unroll 8
    for (int l = 0; l < LEN; l++) s += p[(size_t)l * OUTC];
    out[b * OUTC + o] = s * (1.f / LEN);
}

// ---------------- launch ----------------
extern "C" void kernel_launch(void* const* d_in, const int* in_sizes, int n_in,
                              void* d_out, int out_size) {
    const float* x       = (const float*)d_in[0];
    const float* W_in    = (const float*)d_in[1];
    const float* b_in    = (const float*)d_in[2];
    const float* coeffs1 = (const float*)d_in[3];
    const float* bias1   = (const float*)d_in[4];
    const float* g1      = (const float*)d_in[5];
    const float* beta1   = (const float*)d_in[6];
    const float* coeffs2 = (const float*)d_in[7];
    const float* bias2   = (const float*)d_in[8];
    const float* g2      = (const float*)d_in[9];
    const float* beta2   = (const float*)d_in[10];
    float* out = (float*)d_out;

    cudaFuncSetAttribute(gemm_kan_mma<1>, cudaFuncAttributeMaxDynamicSharedMemorySize, SMEM_GEMM);
    cudaFuncSetAttribute(gemm_kan_mma<2>, cudaFuncAttributeMaxDynamicSharedMemorySize, SMEM_GEMM);

    repackB_kernel<1><<<HID, 256>>>(coeffs1, bias1);
    repackB_kernel<2><<<OUTC, 256>>>(coeffs2, bias2);

    gemm_proj_kernel<<<dim3(HID / GBN, MTOT / GBM), NTHR>>>(x, W_in, b_in);
    splitA_kernel<<<MTOT * 128 / 256, 256>>>();
    gemm_kan_mma<1><<<dim3(HID / 256, MTOT / 128), 256, SMEM_GEMM>>>();
    ln_gelu_split_kernel<<<MTOT, 256>>>(g1, beta1);
    gemm_kan_mma<2><<<dim3(OUTC / 256, MTOT / 128), 256, SMEM_GEMM>>>();
    ln2_kernel<<<MTOT, 256>>>(g2, beta2);
    reduce_kernel<<<BATCH, OUTC>>>(out);
}

// round 5
// speedup vs baseline: 1.6003x; 1.6003x over previous
#include <cuda_runtime.h>
#include <cuda_fp16.h>
#include <cstdint>
#include <math.h>

#define BATCH 16
#define CIN   64
#define LEN   1024
#define HID   1024
#define OUTC  512
#define EPS   1e-5f
#define MTOT  (BATCH*LEN)   // 16384

// GEMM tiling: CTA 128x128, KC=32, 3-stage ring
#define KC     32
#define NK     (HID/KC)      // 32
#define A_ST   49152         // 6 A planes (3 orders x {h,l}) * 128 rows * 64B
#define B_ST   24576         // 3 B planes * 128 rows * 64B
#define STG    (A_ST + B_ST) // 73728
#define NSTG   3
#define SMEM_GEMM (NSTG*STG) // 221184

// fp32 SIMT proj tile params
#define GBM 128
#define GBN 128
#define GBK 16
#define GTM 8
#define GTN 8
#define NTHR 256

// ---------------- scratch ----------------
__device__ __align__(16)  float g_h0[MTOT*HID];
__device__ __align__(16)  float g_h1[MTOT*HID];
__device__ __align__(16)  float g_h2[MTOT*OUTC];
__device__ __align__(128) __half g_A6a[(size_t)MTOT*6144];   // [m][plane(6)][k]
__device__ __align__(128) __half g_A6b[(size_t)MTOT*6144];
__device__ __align__(128) __half g_B3a[(size_t)3*HID*1024];  // [plane(3)][n][k]
__device__ __align__(128) __half g_B3b[(size_t)3*OUTC*1024];
__device__ float g_c01[HID];
__device__ float g_c02[OUTC];
__device__ float g_part[BATCH*16*OUTC];

// ---------------- helpers ----------------
__device__ __forceinline__ uint32_t smem_u32(const void* p) {
    uint32_t a;
    asm("{ .reg .u64 t; cvta.to.shared.u64 t, %1; cvt.u32.u64 %0, t; }" : "=r"(a) : "l"(p));
    return a;
}

#define LDSM_X4(r, addr) \
    asm volatile("ldmatrix.sync.aligned.m8n8.x4.shared.b16 {%0,%1,%2,%3}, [%4];" \
        : "=r"((r)[0]), "=r"((r)[1]), "=r"((r)[2]), "=r"((r)[3]) : "r"(addr))
#define LDSM_X2(r, addr) \
    asm volatile("ldmatrix.sync.aligned.m8n8.x2.shared.b16 {%0,%1}, [%2];" \
        : "=r"((r)[0]), "=r"((r)[1]) : "r"(addr))
#define MMA16816(d, a, b) \
    asm volatile("mma.sync.aligned.m16n8k16.row.col.f32.f16.f16.f32 " \
        "{%0,%1,%2,%3}, {%4,%5,%6,%7}, {%8,%9}, {%0,%1,%2,%3};" \
        : "+f"((d)[0]), "+f"((d)[1]), "+f"((d)[2]), "+f"((d)[3]) \
        : "r"((a)[0]), "r"((a)[1]), "r"((a)[2]), "r"((a)[3]), "r"((b)[0]), "r"((b)[1]))

// ---------------- B repack (single fp16 plane per order) + c0 ----------------
template<int STAGE>
__global__ void repackB_kernel(const float* __restrict__ coeffs, const float* __restrict__ bias) {
    const int N = (STAGE == 1) ? HID : OUTC;
    __half* B3 = (STAGE == 1) ? g_B3a : g_B3b;
    float* c0  = (STAGE == 1) ? g_c01 : g_c02;
    int o = blockIdx.x;
    __shared__ float red[256];
    float s = 0.f;
    #pragma unroll
    for (int it = 0; it < 4; it++) {
        int c = threadIdx.x + it * 256;
        float4 v = *reinterpret_cast<const float4*>(coeffs + ((size_t)o * HID + c) * 4);
        s += v.x;
        size_t base = (size_t)o * 1024 + c;
        size_t ps = (size_t)N * 1024;
        B3[0*ps + base] = __float2half_rn(v.y);
        B3[1*ps + base] = __float2half_rn(v.z);
        B3[2*ps + base] = __float2half_rn(v.w);
    }
    red[threadIdx.x] = s; __syncthreads();
    #pragma unroll
    for (int st = 128; st > 0; st >>= 1) {
        if (threadIdx.x < st) red[threadIdx.x] += red[threadIdx.x + st];
        __syncthreads();
    }
    if (threadIdx.x == 0) c0[o] = red[0] + bias[o];
}

// ---------------- projection GEMM (fp32 SIMT; tiny) ----------------
__global__ void gemm_proj_kernel(const float* __restrict__ x, const float* __restrict__ W,
                                 const float* __restrict__ bias) {
    __shared__ float As[GBK][GBM];
    __shared__ float Bs[GBK][GBN];
    const int m0 = blockIdx.y * GBM, n0 = blockIdx.x * GBN;
    const int tid = threadIdx.x;
    const int tx = tid & 15, ty = tid >> 4;
    float acc[GTM][GTN] = {};
    for (int kt = 0; kt < CIN; kt += GBK) {
        #pragma unroll
        for (int ii = 0; ii < 8; ii++) {
            int idx = tid + ii * NTHR;
            int mm = idx & (GBM - 1);
            int kk = idx >> 7;
            int m = m0 + mm;
            As[kk][mm] = x[((size_t)(m >> 10) * CIN + (kt + kk)) * LEN + (m & 1023)];
        }
        #pragma unroll
        for (int ii = 0; ii < 8; ii++) {
            int idx = tid + ii * NTHR;
            int nn = idx & (GBN - 1);
            int kk = idx >> 7;
            Bs[kk][nn] = W[(size_t)(kt + kk) * HID + n0 + nn];
        }
        __syncthreads();
        #pragma unroll
        for (int kk = 0; kk < GBK; kk++) {
            float a[GTM], bb[GTN];
            #pragma unroll
            for (int i = 0; i < GTM; i++) a[i] = As[kk][ty * GTM + i];
            #pragma unroll
            for (int j = 0; j < GTN; j++) bb[j] = Bs[kk][tx * GTN + j];
            #pragma unroll
            for (int i = 0; i < GTM; i++)
                #pragma unroll
                for (int j = 0; j < GTN; j++)
                    acc[i][j] = fmaf(a[i], bb[j], acc[i][j]);
        }
        __syncthreads();
    }
    #pragma unroll
    for (int i = 0; i < GTM; i++) {
        int m = m0 + ty * GTM + i;
        float* Cp = g_h0 + (size_t)m * HID + n0 + tx * GTN;
        #pragma unroll
        for (int j = 0; j < GTN; j++) Cp[j] = acc[i][j] + bias[n0 + tx * GTN + j];
    }
}

// ---------------- fp16 two-term split store (8 consecutive k) ----------------
__device__ __forceinline__ void split_store8h(__half* dst, const float* v) {
    __half2 h4[4], l4[4];
    #pragma unroll
    for (int q = 0; q < 4; q++) {
        float a = v[2*q], b = v[2*q+1];
        __half ha = __float2half_rn(a), hb = __float2half_rn(b);
        h4[q] = __half2(ha, hb);
        l4[q] = __half2(__float2half_rn(a - __half2float(ha)),
                        __float2half_rn(b - __half2float(hb)));
    }
    *reinterpret_cast<uint4*>(dst)        = *reinterpret_cast<uint4*>(h4);
    *reinterpret_cast<uint4*>(dst + 1024) = *reinterpret_cast<uint4*>(l4);
}

__global__ void splitA_kernel() {
    size_t gid = (size_t)blockIdx.x * 256 + threadIdx.x;   // MTOT*128 threads
    int m = (int)(gid >> 7);
    int k8 = (int)(gid & 127) * 8;
    const float* src = g_h0 + (size_t)m * HID + k8;
    float x1[8], x2[8], x3[8];
    #pragma unroll
    for (int q = 0; q < 2; q++) {
        float4 v = *reinterpret_cast<const float4*>(src + q * 4);
        float* xp = x1 + q * 4;
        xp[0] = v.x; xp[1] = v.y; xp[2] = v.z; xp[3] = v.w;
    }
    #pragma unroll
    for (int i = 0; i < 8; i++) { x2[i] = x1[i] * x1[i]; x3[i] = x2[i] * x1[i]; }
    __half* dst = g_A6a + (size_t)m * 6144 + k8;
    split_store8h(dst,        x1);
    split_store8h(dst + 2048, x2);
    split_store8h(dst + 4096, x3);
}

// ---------------- LN + exact GELU + split ----------------
__device__ __forceinline__ float block_reduce_sum(float v, float* red, int t) {
    red[t] = v; __syncthreads();
    #pragma unroll
    for (int st = 128; st > 0; st >>= 1) {
        if (t < st) red[t] += red[t + st];
        __syncthreads();
    }
    float r = red[0];
    __syncthreads();
    return r;
}

__global__ void ln_gelu_split_kernel(const float* __restrict__ g, const float* __restrict__ beta) {
    __shared__ float red[256];
    int t = threadIdx.x;
    const float* p = g_h1 + (size_t)blockIdx.x * HID;
    float4 v4 = *reinterpret_cast<const float4*>(p + t * 4);
    float v[4] = {v4.x, v4.y, v4.z, v4.w};
    float s = v[0] + v[1] + v[2] + v[3];
    float mu = block_reduce_sum(s, red, t) * (1.f / HID);
    float s2 = 0.f;
    #pragma unroll
    for (int i = 0; i < 4; i++) { float d = v[i] - mu; s2 += d * d; }
    float rstd = rsqrtf(block_reduce_sum(s2, red, t) * (1.f / HID) + EPS);
    const float4 gg = *reinterpret_cast<const float4*>(g + t * 4);
    const float4 bb = *reinterpret_cast<const float4*>(beta + t * 4);
    float y[4];
    y[0] = (v[0] - mu) * rstd * gg.x + bb.x;
    y[1] = (v[1] - mu) * rstd * gg.y + bb.y;
    y[2] = (v[2] - mu) * rstd * gg.z + bb.z;
    y[3] = (v[3] - mu) * rstd * gg.w + bb.w;
    float p1[4], p2[4], p3[4];
    #pragma unroll
    for (int i = 0; i < 4; i++) {
        float yy = y[i];
        yy = 0.5f * yy * (1.f + erff(yy * 0.70710678118654752f));
        p1[i] = yy; p2[i] = yy * yy; p3[i] = p2[i] * yy;
    }
    __half* Ap = g_A6b + (size_t)blockIdx.x * 6144 + t * 4;
    #pragma unroll
    for (int o = 0; o < 3; o++) {
        const float* pp = (o == 0) ? p1 : (o == 1) ? p2 : p3;
        __half2 h2[2], l2[2];
        #pragma unroll
        for (int q = 0; q < 2; q++) {
            float a = pp[2*q], b = pp[2*q+1];
            __half ha = __float2half_rn(a), hb = __float2half_rn(b);
            h2[q] = __half2(ha, hb);
            l2[q] = __half2(__float2half_rn(a - __half2float(ha)),
                            __float2half_rn(b - __half2float(hb)));
        }
        *reinterpret_cast<uint2*>(Ap + o * 2048)        = *reinterpret_cast<uint2*>(h2);
        *reinterpret_cast<uint2*>(Ap + o * 2048 + 1024) = *reinterpret_cast<uint2*>(l2);
    }
}

// ---------------- fused KAN GEMM via fp16 mma.sync (2 MMAs per (o,k16)) ----------------
// smem: A planes pl(0..5)=o*2+hl at bufA + pl*8192 + row*64 + chunk(k8)^swz *16
//       B planes o(0..2)       at bufB + o*8192  + row*64 + chunk^swz *16
__device__ __forceinline__ void load_stage_kan(const __half* A6, const __half* B3,
                                               int N, int m0, int n0, int kt,
                                               uint32_t bufA, uint32_t bufB, int tid) {
    int k0 = kt * KC;
    #pragma unroll
    for (int i = 0; i < 12; i++) {           // A: 6 planes * 128 rows * 4 chunks = 3072
        int id = tid + i * 256;
        int c = id & 3;
        int m = (id >> 2) & 127;
        int pl = id >> 9;
        const void* gp = (const void*)(A6 + (size_t)(m0 + m) * 6144 + pl * 1024 + k0 + c * 8);
        uint32_t sp = bufA + pl * 8192 + m * 64 + ((uint32_t)(c ^ ((m >> 1) & 3)) << 4);
        asm volatile("cp.async.cg.shared.global [%0], [%1], 16;" :: "r"(sp), "l"(gp));
    }
    #pragma unroll
    for (int i = 0; i < 6; i++) {            // B: 3 planes * 128 rows * 4 chunks = 1536
        int id = tid + i * 256;
        int c = id & 3;
        int n = (id >> 2) & 127;
        int pl = id >> 9;
        const void* gp = (const void*)(B3 + (size_t)pl * N * 1024 + (size_t)(n0 + n) * 1024 + k0 + c * 8);
        uint32_t sp = bufB + pl * 8192 + n * 64 + ((uint32_t)(c ^ ((n >> 1) & 3)) << 4);
        asm volatile("cp.async.cg.shared.global [%0], [%1], 16;" :: "r"(sp), "l"(gp));
    }
}

template<int STAGE>
__global__ void __launch_bounds__(256, 1) gemm_kan_mma() {
    const int N        = (STAGE == 1) ? HID : OUTC;
    const __half* A6   = (STAGE == 1) ? g_A6a : g_A6b;
    const __half* B3   = (STAGE == 1) ? g_B3a : g_B3b;
    const float* c0v   = (STAGE == 1) ? g_c01 : g_c02;
    float* C           = (STAGE == 1) ? g_h1 : g_h2;

    extern __shared__ char smem[];
    uint32_t sb = smem_u32(smem);
    int tid = threadIdx.x, lane = tid & 31, w = tid >> 5;
    int wm = w >> 1, wn = w & 1;              // warp grid 4(M) x 2(N); warp tile 32x64
    int m0 = blockIdx.y * 128, n0 = blockIdx.x * 128;

    float acc[2][8][4] = {};

    int hiA = lane >> 4;
    int hiB = (lane >> 3) & 1;
    uint32_t aOff[2]; int aSw[2];
    uint32_t bOff[8]; int bSw[8];
    #pragma unroll
    for (int s = 0; s < 2; s++) {
        int r = wm * 32 + s * 16 + (lane & 15);
        aOff[s] = (uint32_t)r * 64; aSw[s] = (r >> 1) & 3;
    }
    #pragma unroll
    for (int t = 0; t < 8; t++) {
        int r = wn * 64 + t * 8 + (lane & 7);
        bOff[t] = (uint32_t)r * 64; bSw[t] = (r >> 1) & 3;
    }

    // prologue: 2 stages in flight
    load_stage_kan(A6, B3, N, m0, n0, 0, sb, sb + A_ST, tid);
    asm volatile("cp.async.commit_group;" ::: "memory");
    load_stage_kan(A6, B3, N, m0, n0, 1, sb + STG, sb + STG + A_ST, tid);
    asm volatile("cp.async.commit_group;" ::: "memory");

    for (int kt = 0; kt < NK; kt++) {
        asm volatile("cp.async.wait_group 1;" ::: "memory");
        __syncthreads();

        int j = kt + 2;
        if (j < NK) {
            uint32_t nb = sb + (uint32_t)(j % NSTG) * STG;
            load_stage_kan(A6, B3, N, m0, n0, j, nb, nb + A_ST, tid);
        }
        asm volatile("cp.async.commit_group;" ::: "memory");

        uint32_t bufA = sb + (uint32_t)(kt % NSTG) * STG;
        uint32_t bufB = bufA + A_ST;

        #pragma unroll
        for (int o = 0; o < 3; o++) {
            #pragma unroll
            for (int kk = 0; kk < 2; kk++) {
                uint32_t bh[8][2];
                #pragma unroll
                for (int t = 0; t < 8; t++) {
                    uint32_t base = bufB + o * 8192 + bOff[t];
                    LDSM_X2(bh[t], base + ((uint32_t)((kk * 2 + hiB) ^ bSw[t]) << 4));
                }
                #pragma unroll
                for (int s = 0; s < 2; s++) {
                    uint32_t ah[4], al[4];
                    uint32_t baseh = bufA + (2 * o) * 8192 + aOff[s];
                    uint32_t col = (uint32_t)((kk * 2 + hiA) ^ aSw[s]) << 4;
                    LDSM_X4(ah, baseh + col);
                    LDSM_X4(al, baseh + 8192 + col);
                    #pragma unroll
                    for (int t = 0; t < 8; t++) {
                        MMA16816(acc[s][t], ah, bh[t]);
                        MMA16816(acc[s][t], al, bh[t]);
                    }
                }
            }
        }
    }

    // epilogue
    #pragma unroll
    for (int t = 0; t < 8; t++) {
        int col = n0 + wn * 64 + t * 8 + (lane & 3) * 2;
        float c0a = c0v[col], c0b = c0v[col + 1];
        #pragma unroll
        for (int s = 0; s < 2; s++) {
            int r0 = m0 + wm * 32 + s * 16 + (lane >> 2);
            float2 v0 = make_float2(acc[s][t][0] + c0a, acc[s][t][1] + c0b);
            float2 v1 = make_float2(acc[s][t][2] + c0a, acc[s][t][3] + c0b);
            *reinterpret_cast<float2*>(C + (size_t)r0 * N + col) = v0;
            *reinterpret_cast<float2*>(C + (size_t)(r0 + 8) * N + col) = v1;
        }
    }
}

// ---------------- LayerNorm 2 ----------------
__global__ void ln2_kernel(const float* __restrict__ g, const float* __restrict__ beta) {
    __shared__ float red[256];
    int t = threadIdx.x;
    float* p = g_h2 + (size_t)blockIdx.x * OUTC;
    float v[2];
    float s = 0.f;
    #pragma unroll
    for (int i = 0; i < 2; i++) { v[i] = p[t + i * 256]; s += v[i]; }
    float mu = block_reduce_sum(s, red, t) * (1.f / OUTC);
    float s2 = 0.f;
    #pragma unroll
    for (int i = 0; i < 2; i++) { float d = v[i] - mu; s2 += d * d; }
    float rstd = rsqrtf(block_reduce_sum(s2, red, t) * (1.f / OUTC) + EPS);
    #pragma unroll
    for (int i = 0; i < 2; i++) {
        int o = t + i * 256;
        p[o] = (v[i] - mu) * rstd * g[o] + beta[o];
    }
}

// ---------------- mean over L (two-phase, deterministic) ----------------
__global__ void reduce1_kernel() {
    int b = blockIdx.y, seg = blockIdx.x;     // 16 segs of 64 rows
    int o = threadIdx.x;                      // 512
    const float* p = g_h2 + ((size_t)b * LEN + seg * 64) * OUTC + o;
    float s = 0.f;
    #pragma unroll 8
    for (int l = 0; l < 64; l++) s += p[(size_t)l * OUTC];
    g_part[((size_t)b * 16 + seg) * OUTC + o] = s;
}

__global__ void reduce2_kernel(float* __restrict__ out) {
    int b = blockIdx.x, o = threadIdx.x;
    const float* p = g_part + (size_t)b * 16 * OUTC + o;
    float s = 0.f;
    #pragma unroll
    for (int seg = 0; seg < 16; seg++) s += p[(size_t)seg * OUTC];
    out[b * OUTC + o] = s * (1.f / LEN);
}

// ---------------- launch ----------------
extern "C" void kernel_launch(void* const* d_in, const int* in_sizes, int n_in,
                              void* d_out, int out_size) {
    const float* x       = (const float*)d_in[0];
    const float* W_in    = (const float*)d_in[1];
    const float* b_in    = (const float*)d_in[2];
    const float* coeffs1 = (const float*)d_in[3];
    const float* bias1   = (const float*)d_in[4];
    const float* g1      = (const float*)d_in[5];
    const float* beta1   = (const float*)d_in[6];
    const float* coeffs2 = (const float*)d_in[7];
    const float* bias2   = (const float*)d_in[8];
    const float* g2      = (const float*)d_in[9];
    const float* beta2   = (const float*)d_in[10];
    float* out = (float*)d_out;

    cudaFuncSetAttribute(gemm_kan_mma<1>, cudaFuncAttributeMaxDynamicSharedMemorySize, SMEM_GEMM);
    cudaFuncSetAttribute(gemm_kan_mma<2>, cudaFuncAttributeMaxDynamicSharedMemorySize, SMEM_GEMM);

    repackB_kernel<1><<<HID, 256>>>(coeffs1, bias1);
    repackB_kernel<2><<<OUTC, 256>>>(coeffs2, bias2);

    gemm_proj_kernel<<<dim3(HID / GBN, MTOT / GBM), NTHR>>>(x, W_in, b_in);
    splitA_kernel<<<MTOT * 128 / 256, 256>>>();
    gemm_kan_mma<1><<<dim3(HID / 128, MTOT / 128), 256, SMEM_GEMM>>>();
    ln_gelu_split_kernel<<<MTOT, 256>>>(g1, beta1);
    gemm_kan_mma<2><<<dim3(OUTC / 128, MTOT / 128), 256, SMEM_GEMM>>>();
    ln2_kernel<<<MTOT, 256>>>(g2, beta2);
    reduce1_kernel<<<dim3(16, BATCH), OUTC>>>();
    reduce2_kernel<<<BATCH, OUTC>>>(out);
}

// round 6
// speedup vs baseline: 2.5305x; 1.5813x over previous
#include <cuda_runtime.h>
#include <cuda_fp16.h>
#include <cstdint>
#include <math.h>

#define BATCH 16
#define CIN   64
#define LEN   1024
#define HID   1024
#define OUTC  512
#define EPS   1e-5f
#define MTOT  (BATCH*LEN)   // 16384

// GEMM tiling: CTA 128x128, KC=32, 4-stage ring
#define KC     32
#define NK     (HID/KC)      // 32
#define A_ST   24576         // 3 A planes (orders, fp16) * 128 rows * 64B
#define B_ST   24576         // 3 B planes * 128 rows * 64B
#define STG    (A_ST + B_ST) // 49152
#define NSTG   4
#define SMEM_GEMM (NSTG*STG) // 196608

// fp32 SIMT proj tile params
#define GBM 128
#define GBN 128
#define GBK 16
#define GTM 8
#define GTN 8
#define NTHR 256

// ---------------- scratch ----------------
__device__ __align__(16)  float g_h1[MTOT*HID];
__device__ __align__(16)  float g_h2[MTOT*OUTC];
__device__ __align__(128) __half g_A3a[(size_t)MTOT*3072];   // [m][order(3)][k]  96MB
__device__ __align__(128) __half g_A3b[(size_t)MTOT*3072];   // 96MB
__device__ __align__(128) __half g_B3a[(size_t)3*HID*1024];  // [order][n][k] 6MB
__device__ __align__(128) __half g_B3b[(size_t)3*OUTC*1024]; // 3MB
__device__ float g_c01[HID];
__device__ float g_c02[OUTC];
__device__ float g_part[BATCH*16*OUTC];

// ---------------- helpers ----------------
__device__ __forceinline__ uint32_t smem_u32(const void* p) {
    uint32_t a;
    asm("{ .reg .u64 t; cvta.to.shared.u64 t, %1; cvt.u32.u64 %0, t; }" : "=r"(a) : "l"(p));
    return a;
}

#define LDSM_X4(r, addr) \
    asm volatile("ldmatrix.sync.aligned.m8n8.x4.shared.b16 {%0,%1,%2,%3}, [%4];" \
        : "=r"((r)[0]), "=r"((r)[1]), "=r"((r)[2]), "=r"((r)[3]) : "r"(addr))
#define LDSM_X2(r, addr) \
    asm volatile("ldmatrix.sync.aligned.m8n8.x2.shared.b16 {%0,%1}, [%2];" \
        : "=r"((r)[0]), "=r"((r)[1]) : "r"(addr))
#define MMA16816(d, a, b) \
    asm volatile("mma.sync.aligned.m16n8k16.row.col.f32.f16.f16.f32 " \
        "{%0,%1,%2,%3}, {%4,%5,%6,%7}, {%8,%9}, {%0,%1,%2,%3};" \
        : "+f"((d)[0]), "+f"((d)[1]), "+f"((d)[2]), "+f"((d)[3]) \
        : "r"((a)[0]), "r"((a)[1]), "r"((a)[2]), "r"((a)[3]), "r"((b)[0]), "r"((b)[1]))

// ---------------- B repack (single fp16 plane per order) + c0 ----------------
template<int STAGE>
__global__ void repackB_kernel(const float* __restrict__ coeffs, const float* __restrict__ bias) {
    const int N = (STAGE == 1) ? HID : OUTC;
    __half* B3 = (STAGE == 1) ? g_B3a : g_B3b;
    float* c0  = (STAGE == 1) ? g_c01 : g_c02;
    int o = blockIdx.x;
    __shared__ float red[256];
    float s = 0.f;
    #pragma unroll
    for (int it = 0; it < 4; it++) {
        int c = threadIdx.x + it * 256;
        float4 v = *reinterpret_cast<const float4*>(coeffs + ((size_t)o * HID + c) * 4);
        s += v.x;
        size_t base = (size_t)o * 1024 + c;
        size_t ps = (size_t)N * 1024;
        B3[0*ps + base] = __float2half_rn(v.y);
        B3[1*ps + base] = __float2half_rn(v.z);
        B3[2*ps + base] = __float2half_rn(v.w);
    }
    red[threadIdx.x] = s; __syncthreads();
    #pragma unroll
    for (int st = 128; st > 0; st >>= 1) {
        if (threadIdx.x < st) red[threadIdx.x] += red[threadIdx.x + st];
        __syncthreads();
    }
    if (threadIdx.x == 0) c0[o] = red[0] + bias[o];
}

// ---------------- projection GEMM (fp32 SIMT) + fused power split to fp16 ----------------
__global__ void gemm_proj_kernel(const float* __restrict__ x, const float* __restrict__ W,
                                 const float* __restrict__ bias) {
    __shared__ float As[GBK][GBM];
    __shared__ float Bs[GBK][GBN];
    const int m0 = blockIdx.y * GBM, n0 = blockIdx.x * GBN;
    const int tid = threadIdx.x;
    const int tx = tid & 15, ty = tid >> 4;
    float acc[GTM][GTN] = {};
    for (int kt = 0; kt < CIN; kt += GBK) {
        #pragma unroll
        for (int ii = 0; ii < 8; ii++) {
            int idx = tid + ii * NTHR;
            int mm = idx & (GBM - 1);
            int kk = idx >> 7;
            int m = m0 + mm;
            As[kk][mm] = x[((size_t)(m >> 10) * CIN + (kt + kk)) * LEN + (m & 1023)];
        }
        #pragma unroll
        for (int ii = 0; ii < 8; ii++) {
            int idx = tid + ii * NTHR;
            int nn = idx & (GBN - 1);
            int kk = idx >> 7;
            Bs[kk][nn] = W[(size_t)(kt + kk) * HID + n0 + nn];
        }
        __syncthreads();
        #pragma unroll
        for (int kk = 0; kk < GBK; kk++) {
            float a[GTM], bb[GTN];
            #pragma unroll
            for (int i = 0; i < GTM; i++) a[i] = As[kk][ty * GTM + i];
            #pragma unroll
            for (int j = 0; j < GTN; j++) bb[j] = Bs[kk][tx * GTN + j];
            #pragma unroll
            for (int i = 0; i < GTM; i++)
                #pragma unroll
                for (int j = 0; j < GTN; j++)
                    acc[i][j] = fmaf(a[i], bb[j], acc[i][j]);
        }
        __syncthreads();
    }
    float bv[GTN];
    #pragma unroll
    for (int j = 0; j < GTN; j++) bv[j] = bias[n0 + tx * GTN + j];
    #pragma unroll
    for (int i = 0; i < GTM; i++) {
        int m = m0 + ty * GTM + i;
        __half* dst = g_A3a + (size_t)m * 3072 + n0 + tx * GTN;
        __half2 p1[4], p2[4], p3[4];
        #pragma unroll
        for (int q = 0; q < 4; q++) {
            float a = acc[i][2*q]   + bv[2*q];
            float b = acc[i][2*q+1] + bv[2*q+1];
            float a2 = a * a, b2 = b * b;
            p1[q] = __half2(__float2half_rn(a),     __float2half_rn(b));
            p2[q] = __half2(__float2half_rn(a2),    __float2half_rn(b2));
            p3[q] = __half2(__float2half_rn(a2*a),  __float2half_rn(b2*b));
        }
        *reinterpret_cast<uint4*>(dst)        = *reinterpret_cast<uint4*>(p1);
        *reinterpret_cast<uint4*>(dst + 1024) = *reinterpret_cast<uint4*>(p2);
        *reinterpret_cast<uint4*>(dst + 2048) = *reinterpret_cast<uint4*>(p3);
    }
}

// ---------------- LN + exact GELU + fp16 power split ----------------
__device__ __forceinline__ float block_reduce_sum(float v, float* red, int t) {
    red[t] = v; __syncthreads();
    #pragma unroll
    for (int st = 128; st > 0; st >>= 1) {
        if (t < st) red[t] += red[t + st];
        __syncthreads();
    }
    float r = red[0];
    __syncthreads();
    return r;
}

__global__ void ln_gelu_split_kernel(const float* __restrict__ g, const float* __restrict__ beta) {
    __shared__ float red[256];
    int t = threadIdx.x;
    const float* p = g_h1 + (size_t)blockIdx.x * HID;
    float4 v4 = *reinterpret_cast<const float4*>(p + t * 4);
    float v[4] = {v4.x, v4.y, v4.z, v4.w};
    float s = v[0] + v[1] + v[2] + v[3];
    float mu = block_reduce_sum(s, red, t) * (1.f / HID);
    float s2 = 0.f;
    #pragma unroll
    for (int i = 0; i < 4; i++) { float d = v[i] - mu; s2 += d * d; }
    float rstd = rsqrtf(block_reduce_sum(s2, red, t) * (1.f / HID) + EPS);
    const float4 gg = *reinterpret_cast<const float4*>(g + t * 4);
    const float4 bb = *reinterpret_cast<const float4*>(beta + t * 4);
    float y[4];
    y[0] = (v[0] - mu) * rstd * gg.x + bb.x;
    y[1] = (v[1] - mu) * rstd * gg.y + bb.y;
    y[2] = (v[2] - mu) * rstd * gg.z + bb.z;
    y[3] = (v[3] - mu) * rstd * gg.w + bb.w;
    float p1[4], p2[4], p3[4];
    #pragma unroll
    for (int i = 0; i < 4; i++) {
        float yy = y[i];
        yy = 0.5f * yy * (1.f + erff(yy * 0.70710678118654752f));
        p1[i] = yy; p2[i] = yy * yy; p3[i] = p2[i] * yy;
    }
    __half* Ap = g_A3b + (size_t)blockIdx.x * 3072 + t * 4;
    #pragma unroll
    for (int o = 0; o < 3; o++) {
        const float* pp = (o == 0) ? p1 : (o == 1) ? p2 : p3;
        __half2 h2[2];
        h2[0] = __half2(__float2half_rn(pp[0]), __float2half_rn(pp[1]));
        h2[1] = __half2(__float2half_rn(pp[2]), __float2half_rn(pp[3]));
        *reinterpret_cast<uint2*>(Ap + o * 1024) = *reinterpret_cast<uint2*>(h2);
    }
}

// ---------------- fused KAN GEMM via fp16 mma.sync (1 MMA per (o,k16)) ----------------
__device__ __forceinline__ void load_stage_kan(const __half* A3, const __half* B3,
                                               int N, int m0, int n0, int kt,
                                               uint32_t bufA, uint32_t bufB, int tid) {
    int k0 = kt * KC;
    #pragma unroll
    for (int i = 0; i < 6; i++) {            // A: 3 planes * 128 rows * 4 chunks = 1536
        int id = tid + i * 256;
        int c = id & 3;
        int m = (id >> 2) & 127;
        int pl = id >> 9;
        const void* gp = (const void*)(A3 + (size_t)(m0 + m) * 3072 + pl * 1024 + k0 + c * 8);
        uint32_t sp = bufA + pl * 8192 + m * 64 + ((uint32_t)(c ^ ((m >> 1) & 3)) << 4);
        asm volatile("cp.async.cg.shared.global [%0], [%1], 16;" :: "r"(sp), "l"(gp));
    }
    #pragma unroll
    for (int i = 0; i < 6; i++) {            // B: 3 planes * 128 rows * 4 chunks = 1536
        int id = tid + i * 256;
        int c = id & 3;
        int n = (id >> 2) & 127;
        int pl = id >> 9;
        const void* gp = (const void*)(B3 + (size_t)pl * N * 1024 + (size_t)(n0 + n) * 1024 + k0 + c * 8);
        uint32_t sp = bufB + pl * 8192 + n * 64 + ((uint32_t)(c ^ ((n >> 1) & 3)) << 4);
        asm volatile("cp.async.cg.shared.global [%0], [%1], 16;" :: "r"(sp), "l"(gp));
    }
}

template<int STAGE>
__global__ void __launch_bounds__(256, 1) gemm_kan_mma() {
    const int N      = (STAGE == 1) ? HID : OUTC;
    const __half* A3 = (STAGE == 1) ? g_A3a : g_A3b;
    const __half* B3 = (STAGE == 1) ? g_B3a : g_B3b;
    const float* c0v = (STAGE == 1) ? g_c01 : g_c02;
    float* C         = (STAGE == 1) ? g_h1 : g_h2;

    extern __shared__ char smem[];
    uint32_t sb = smem_u32(smem);
    int tid = threadIdx.x, lane = tid & 31, w = tid >> 5;
    int wm = w >> 1, wn = w & 1;              // warp grid 4(M) x 2(N); warp tile 32x64
    int m0 = blockIdx.y * 128, n0 = blockIdx.x * 128;

    float acc[2][8][4] = {};

    int hiA = lane >> 4;
    int hiB = (lane >> 3) & 1;
    uint32_t aOff[2]; int aSw[2];
    uint32_t bOff[8]; int bSw[8];
    #pragma unroll
    for (int s = 0; s < 2; s++) {
        int r = wm * 32 + s * 16 + (lane & 15);
        aOff[s] = (uint32_t)r * 64; aSw[s] = (r >> 1) & 3;
    }
    #pragma unroll
    for (int t = 0; t < 8; t++) {
        int r = wn * 64 + t * 8 + (lane & 7);
        bOff[t] = (uint32_t)r * 64; bSw[t] = (r >> 1) & 3;
    }

    // prologue: 3 stages in flight
    #pragma unroll
    for (int s = 0; s < 3; s++) {
        load_stage_kan(A3, B3, N, m0, n0, s, sb + s * STG, sb + s * STG + A_ST, tid);
        asm volatile("cp.async.commit_group;" ::: "memory");
    }

    for (int kt = 0; kt < NK; kt++) {
        asm volatile("cp.async.wait_group 2;" ::: "memory");
        __syncthreads();

        int j = kt + 3;
        if (j < NK) {
            uint32_t nb = sb + (uint32_t)(j & (NSTG - 1)) * STG;
            load_stage_kan(A3, B3, N, m0, n0, j, nb, nb + A_ST, tid);
        }
        asm volatile("cp.async.commit_group;" ::: "memory");

        uint32_t bufA = sb + (uint32_t)(kt & (NSTG - 1)) * STG;
        uint32_t bufB = bufA + A_ST;

        #pragma unroll
        for (int o = 0; o < 3; o++) {
            #pragma unroll
            for (int kk = 0; kk < 2; kk++) {
                uint32_t bh[8][2];
                #pragma unroll
                for (int t = 0; t < 8; t++) {
                    uint32_t base = bufB + o * 8192 + bOff[t];
                    LDSM_X2(bh[t], base + ((uint32_t)((kk * 2 + hiB) ^ bSw[t]) << 4));
                }
                #pragma unroll
                for (int s = 0; s < 2; s++) {
                    uint32_t ah[4];
                    uint32_t base = bufA + o * 8192 + aOff[s];
                    LDSM_X4(ah, base + ((uint32_t)((kk * 2 + hiA) ^ aSw[s]) << 4));
                    #pragma unroll
                    for (int t = 0; t < 8; t++)
                        MMA16816(acc[s][t], ah, bh[t]);
                }
            }
        }
    }

    // epilogue
    #pragma unroll
    for (int t = 0; t < 8; t++) {
        int col = n0 + wn * 64 + t * 8 + (lane & 3) * 2;
        float c0a = c0v[col], c0b = c0v[col + 1];
        #pragma unroll
        for (int s = 0; s < 2; s++) {
            int r0 = m0 + wm * 32 + s * 16 + (lane >> 2);
            float2 v0 = make_float2(acc[s][t][0] + c0a, acc[s][t][1] + c0b);
            float2 v1 = make_float2(acc[s][t][2] + c0a, acc[s][t][3] + c0b);
            *reinterpret_cast<float2*>(C + (size_t)r0 * N + col) = v0;
            *reinterpret_cast<float2*>(C + (size_t)(r0 + 8) * N + col) = v1;
        }
    }
}

// ---------------- LayerNorm 2 ----------------
__global__ void ln2_kernel(const float* __restrict__ g, const float* __restrict__ beta) {
    __shared__ float red[256];
    int t = threadIdx.x;
    float* p = g_h2 + (size_t)blockIdx.x * OUTC;
    float v[2];
    float s = 0.f;
    #pragma unroll
    for (int i = 0; i < 2; i++) { v[i] = p[t + i * 256]; s += v[i]; }
    float mu = block_reduce_sum(s, red, t) * (1.f / OUTC);
    float s2 = 0.f;
    #pragma unroll
    for (int i = 0; i < 2; i++) { float d = v[i] - mu; s2 += d * d; }
    float rstd = rsqrtf(block_reduce_sum(s2, red, t) * (1.f / OUTC) + EPS);
    #pragma unroll
    for (int i = 0; i < 2; i++) {
        int o = t + i * 256;
        p[o] = (v[i] - mu) * rstd * g[o] + beta[o];
    }
}

// ---------------- mean over L (two-phase, deterministic) ----------------
__global__ void reduce1_kernel() {
    int b = blockIdx.y, seg = blockIdx.x;
    int o = threadIdx.x;
    const float* p = g_h2 + ((size_t)b * LEN + seg * 64) * OUTC + o;
    float s = 0.f;
    #pragma unroll 8
    for (int l = 0; l < 64; l++) s += p[(size_t)l * OUTC];
    g_part[((size_t)b * 16 + seg) * OUTC + o] = s;
}

__global__ void reduce2_kernel(float* __restrict__ out) {
    int b = blockIdx.x, o = threadIdx.x;
    const float* p = g_part + (size_t)b * 16 * OUTC + o;
    float s = 0.f;
    #pragma unroll
    for (int seg = 0; seg < 16; seg++) s += p[(size_t)seg * OUTC];
    out[b * OUTC + o] = s * (1.f / LEN);
}

// ---------------- launch ----------------
extern "C" void kernel_launch(void* const* d_in, const int* in_sizes, int n_in,
                              void* d_out, int out_size) {
    const float* x       = (const float*)d_in[0];
    const float* W_in    = (const float*)d_in[1];
    const float* b_in    = (const float*)d_in[2];
    const float* coeffs1 = (const float*)d_in[3];
    const float* bias1   = (const float*)d_in[4];
    const float* g1      = (const float*)d_in[5];
    const float* beta1   = (const float*)d_in[6];
    const float* coeffs2 = (const float*)d_in[7];
    const float* bias2   = (const float*)d_in[8];
    const float* g2      = (const float*)d_in[9];
    const float* beta2   = (const float*)d_in[10];
    float* out = (float*)d_out;

    cudaFuncSetAttribute(gemm_kan_mma<1>, cudaFuncAttributeMaxDynamicSharedMemorySize, SMEM_GEMM);
    cudaFuncSetAttribute(gemm_kan_mma<2>, cudaFuncAttributeMaxDynamicSharedMemorySize, SMEM_GEMM);

    repackB_kernel<1><<<HID, 256>>>(coeffs1, bias1);
    repackB_kernel<2><<<OUTC, 256>>>(coeffs2, bias2);

    gemm_proj_kernel<<<dim3(HID / GBN, MTOT / GBM), NTHR>>>(x, W_in, b_in);
    gemm_kan_mma<1><<<dim3(HID / 128, MTOT / 128), 256, SMEM_GEMM>>>();
    ln_gelu_split_kernel<<<MTOT, 256>>>(g1, beta1);
    gemm_kan_mma<2><<<dim3(OUTC / 128, MTOT / 128), 256, SMEM_GEMM>>>();
    ln2_kernel<<<MTOT, 256>>>(g2, beta2);
    reduce1_kernel<<<dim3(16, BATCH), OUTC>>>();
    reduce2_kernel<<<BATCH, OUTC>>>(out);
}

// round 7
// speedup vs baseline: 2.8587x; 1.1297x over previous
#include <cuda_runtime.h>
#include <cuda_fp16.h>
#include <cstdint>
#include <math.h>

#define BATCH 16
#define CIN   64
#define LEN   1024
#define HID   1024
#define OUTC  512
#define EPS   1e-5f
#define MTOT  (BATCH*LEN)   // 16384

// GEMM tiling: CTA 128x128, KC=32, 2-stage double buffer, 2 CTAs/SM
#define KC     32
#define NK     (HID/KC)      // 32
#define A_ST   24576         // 3 A planes (orders, fp16) * 128 rows * 64B
#define B_ST   24576         // 3 B planes * 128 rows * 64B
#define STG    (A_ST + B_ST) // 49152
#define NSTG   2
#define SMEM_GEMM (NSTG*STG) // 98304

// fp32 SIMT proj tile params
#define GBM 128
#define GBN 128
#define GBK 16
#define GTM 8
#define GTN 8
#define NTHR 256

// ---------------- scratch ----------------
__device__ __align__(16)  float g_h1[MTOT*HID];
__device__ __align__(16)  float g_h2[MTOT*OUTC];
__device__ __align__(128) __half g_A3a[(size_t)MTOT*3072];   // [m][order(3)][k]
__device__ __align__(128) __half g_A3b[(size_t)MTOT*3072];
__device__ __align__(128) __half g_B3a[(size_t)3*HID*1024];  // [order][n][k]
__device__ __align__(128) __half g_B3b[(size_t)3*OUTC*1024];
__device__ float g_c01[HID];
__device__ float g_c02[OUTC];
__device__ float g_part[BATCH*16*OUTC];

// ---------------- helpers ----------------
__device__ __forceinline__ uint32_t smem_u32(const void* p) {
    uint32_t a;
    asm("{ .reg .u64 t; cvta.to.shared.u64 t, %1; cvt.u32.u64 %0, t; }" : "=r"(a) : "l"(p));
    return a;
}

#define LDSM_X4(r, addr) \
    asm volatile("ldmatrix.sync.aligned.m8n8.x4.shared.b16 {%0,%1,%2,%3}, [%4];" \
        : "=r"((r)[0]), "=r"((r)[1]), "=r"((r)[2]), "=r"((r)[3]) : "r"(addr))
#define LDSM_X2(r, addr) \
    asm volatile("ldmatrix.sync.aligned.m8n8.x2.shared.b16 {%0,%1}, [%2];" \
        : "=r"((r)[0]), "=r"((r)[1]) : "r"(addr))
#define MMA16816(d, a, b) \
    asm volatile("mma.sync.aligned.m16n8k16.row.col.f32.f16.f16.f32 " \
        "{%0,%1,%2,%3}, {%4,%5,%6,%7}, {%8,%9}, {%0,%1,%2,%3};" \
        : "+f"((d)[0]), "+f"((d)[1]), "+f"((d)[2]), "+f"((d)[3]) \
        : "r"((a)[0]), "r"((a)[1]), "r"((a)[2]), "r"((a)[3]), "r"((b)[0]), "r"((b)[1]))

// ---------------- B repack (single fp16 plane per order) + c0 ----------------
template<int STAGE>
__global__ void repackB_kernel(const float* __restrict__ coeffs, const float* __restrict__ bias) {
    const int N = (STAGE == 1) ? HID : OUTC;
    __half* B3 = (STAGE == 1) ? g_B3a : g_B3b;
    float* c0  = (STAGE == 1) ? g_c01 : g_c02;
    int o = blockIdx.x;
    __shared__ float red[256];
    float s = 0.f;
    #pragma unroll
    for (int it = 0; it < 4; it++) {
        int c = threadIdx.x + it * 256;
        float4 v = *reinterpret_cast<const float4*>(coeffs + ((size_t)o * HID + c) * 4);
        s += v.x;
        size_t base = (size_t)o * 1024 + c;
        size_t ps = (size_t)N * 1024;
        B3[0*ps + base] = __float2half_rn(v.y);
        B3[1*ps + base] = __float2half_rn(v.z);
        B3[2*ps + base] = __float2half_rn(v.w);
    }
    red[threadIdx.x] = s; __syncthreads();
    #pragma unroll
    for (int st = 128; st > 0; st >>= 1) {
        if (threadIdx.x < st) red[threadIdx.x] += red[threadIdx.x + st];
        __syncthreads();
    }
    if (threadIdx.x == 0) c0[o] = red[0] + bias[o];
}

// ---------------- projection GEMM (fp32 SIMT) + fused power split to fp16 ----------------
__global__ void gemm_proj_kernel(const float* __restrict__ x, const float* __restrict__ W,
                                 const float* __restrict__ bias) {
    __shared__ float As[GBK][GBM];
    __shared__ float Bs[GBK][GBN];
    const int m0 = blockIdx.y * GBM, n0 = blockIdx.x * GBN;
    const int tid = threadIdx.x;
    const int tx = tid & 15, ty = tid >> 4;
    float acc[GTM][GTN] = {};
    for (int kt = 0; kt < CIN; kt += GBK) {
        #pragma unroll
        for (int ii = 0; ii < 8; ii++) {
            int idx = tid + ii * NTHR;
            int mm = idx & (GBM - 1);
            int kk = idx >> 7;
            int m = m0 + mm;
            As[kk][mm] = x[((size_t)(m >> 10) * CIN + (kt + kk)) * LEN + (m & 1023)];
        }
        #pragma unroll
        for (int ii = 0; ii < 8; ii++) {
            int idx = tid + ii * NTHR;
            int nn = idx & (GBN - 1);
            int kk = idx >> 7;
            Bs[kk][nn] = W[(size_t)(kt + kk) * HID + n0 + nn];
        }
        __syncthreads();
        #pragma unroll
        for (int kk = 0; kk < GBK; kk++) {
            float a[GTM], bb[GTN];
            #pragma unroll
            for (int i = 0; i < GTM; i++) a[i] = As[kk][ty * GTM + i];
            #pragma unroll
            for (int j = 0; j < GTN; j++) bb[j] = Bs[kk][tx * GTN + j];
            #pragma unroll
            for (int i = 0; i < GTM; i++)
                #pragma unroll
                for (int j = 0; j < GTN; j++)
                    acc[i][j] = fmaf(a[i], bb[j], acc[i][j]);
        }
        __syncthreads();
    }
    float bv[GTN];
    #pragma unroll
    for (int j = 0; j < GTN; j++) bv[j] = bias[n0 + tx * GTN + j];
    #pragma unroll
    for (int i = 0; i < GTM; i++) {
        int m = m0 + ty * GTM + i;
        __half* dst = g_A3a + (size_t)m * 3072 + n0 + tx * GTN;
        __half2 p1[4], p2[4], p3[4];
        #pragma unroll
        for (int q = 0; q < 4; q++) {
            float a = acc[i][2*q]   + bv[2*q];
            float b = acc[i][2*q+1] + bv[2*q+1];
            float a2 = a * a, b2 = b * b;
            p1[q] = __half2(__float2half_rn(a),     __float2half_rn(b));
            p2[q] = __half2(__float2half_rn(a2),    __float2half_rn(b2));
            p3[q] = __half2(__float2half_rn(a2*a),  __float2half_rn(b2*b));
        }
        *reinterpret_cast<uint4*>(dst)        = *reinterpret_cast<uint4*>(p1);
        *reinterpret_cast<uint4*>(dst + 1024) = *reinterpret_cast<uint4*>(p2);
        *reinterpret_cast<uint4*>(dst + 2048) = *reinterpret_cast<uint4*>(p3);
    }
}

// ---------------- LN + exact GELU + fp16 power split ----------------
__device__ __forceinline__ float block_reduce_sum(float v, float* red, int t) {
    red[t] = v; __syncthreads();
    #pragma unroll
    for (int st = 128; st > 0; st >>= 1) {
        if (t < st) red[t] += red[t + st];
        __syncthreads();
    }
    float r = red[0];
    __syncthreads();
    return r;
}

__global__ void ln_gelu_split_kernel(const float* __restrict__ g, const float* __restrict__ beta) {
    __shared__ float red[256];
    int t = threadIdx.x;
    const float* p = g_h1 + (size_t)blockIdx.x * HID;
    float4 v4 = *reinterpret_cast<const float4*>(p + t * 4);
    float v[4] = {v4.x, v4.y, v4.z, v4.w};
    float s = v[0] + v[1] + v[2] + v[3];
    float mu = block_reduce_sum(s, red, t) * (1.f / HID);
    float s2 = 0.f;
    #pragma unroll
    for (int i = 0; i < 4; i++) { float d = v[i] - mu; s2 += d * d; }
    float rstd = rsqrtf(block_reduce_sum(s2, red, t) * (1.f / HID) + EPS);
    const float4 gg = *reinterpret_cast<const float4*>(g + t * 4);
    const float4 bb = *reinterpret_cast<const float4*>(beta + t * 4);
    float y[4];
    y[0] = (v[0] - mu) * rstd * gg.x + bb.x;
    y[1] = (v[1] - mu) * rstd * gg.y + bb.y;
    y[2] = (v[2] - mu) * rstd * gg.z + bb.z;
    y[3] = (v[3] - mu) * rstd * gg.w + bb.w;
    float p1[4], p2[4], p3[4];
    #pragma unroll
    for (int i = 0; i < 4; i++) {
        float yy = y[i];
        yy = 0.5f * yy * (1.f + erff(yy * 0.70710678118654752f));
        p1[i] = yy; p2[i] = yy * yy; p3[i] = p2[i] * yy;
    }
    __half* Ap = g_A3b + (size_t)blockIdx.x * 3072 + t * 4;
    #pragma unroll
    for (int o = 0; o < 3; o++) {
        const float* pp = (o == 0) ? p1 : (o == 1) ? p2 : p3;
        __half2 h2[2];
        h2[0] = __half2(__float2half_rn(pp[0]), __float2half_rn(pp[1]));
        h2[1] = __half2(__float2half_rn(pp[2]), __float2half_rn(pp[3]));
        *reinterpret_cast<uint2*>(Ap + o * 1024) = *reinterpret_cast<uint2*>(h2);
    }
}

// ---------------- fused KAN GEMM via fp16 mma.sync (1 MMA per (o,k16)) ----------------
__device__ __forceinline__ void load_stage_kan(const __half* A3, const __half* B3,
                                               int N, int m0, int n0, int kt,
                                               uint32_t bufA, uint32_t bufB, int tid) {
    int k0 = kt * KC;
    #pragma unroll
    for (int i = 0; i < 6; i++) {            // A: 3 planes * 128 rows * 4 chunks = 1536
        int id = tid + i * 256;
        int c = id & 3;
        int m = (id >> 2) & 127;
        int pl = id >> 9;
        const void* gp = (const void*)(A3 + (size_t)(m0 + m) * 3072 + pl * 1024 + k0 + c * 8);
        uint32_t sp = bufA + pl * 8192 + m * 64 + ((uint32_t)(c ^ ((m >> 1) & 3)) << 4);
        asm volatile("cp.async.cg.shared.global [%0], [%1], 16;" :: "r"(sp), "l"(gp));
    }
    #pragma unroll
    for (int i = 0; i < 6; i++) {            // B: 3 planes * 128 rows * 4 chunks = 1536
        int id = tid + i * 256;
        int c = id & 3;
        int n = (id >> 2) & 127;
        int pl = id >> 9;
        const void* gp = (const void*)(B3 + (size_t)pl * N * 1024 + (size_t)(n0 + n) * 1024 + k0 + c * 8);
        uint32_t sp = bufB + pl * 8192 + n * 64 + ((uint32_t)(c ^ ((n >> 1) & 3)) << 4);
        asm volatile("cp.async.cg.shared.global [%0], [%1], 16;" :: "r"(sp), "l"(gp));
    }
}

template<int STAGE>
__global__ void __launch_bounds__(256, 2) gemm_kan_mma() {
    const int N      = (STAGE == 1) ? HID : OUTC;
    const __half* A3 = (STAGE == 1) ? g_A3a : g_A3b;
    const __half* B3 = (STAGE == 1) ? g_B3a : g_B3b;
    const float* c0v = (STAGE == 1) ? g_c01 : g_c02;
    float* C         = (STAGE == 1) ? g_h1 : g_h2;

    extern __shared__ char smem[];
    uint32_t sb = smem_u32(smem);
    int tid = threadIdx.x, lane = tid & 31, w = tid >> 5;
    int wm = w >> 1, wn = w & 1;              // warp grid 4(M) x 2(N); warp tile 32x64
    int m0 = blockIdx.y * 128, n0 = blockIdx.x * 128;

    float acc[2][8][4] = {};

    int hiA = lane >> 4;
    int hiB = (lane >> 3) & 1;
    uint32_t aOff[2]; int aSw[2];
    uint32_t bOff[8]; int bSw[8];
    #pragma unroll
    for (int s = 0; s < 2; s++) {
        int r = wm * 32 + s * 16 + (lane & 15);
        aOff[s] = (uint32_t)r * 64; aSw[s] = (r >> 1) & 3;
    }
    #pragma unroll
    for (int t = 0; t < 8; t++) {
        int r = wn * 64 + t * 8 + (lane & 7);
        bOff[t] = (uint32_t)r * 64; bSw[t] = (r >> 1) & 3;
    }

    // prologue: both stages in flight
    load_stage_kan(A3, B3, N, m0, n0, 0, sb, sb + A_ST, tid);
    asm volatile("cp.async.commit_group;" ::: "memory");
    load_stage_kan(A3, B3, N, m0, n0, 1, sb + STG, sb + STG + A_ST, tid);
    asm volatile("cp.async.commit_group;" ::: "memory");

    for (int kt = 0; kt < NK; kt++) {
        asm volatile("cp.async.wait_group 1;" ::: "memory");
        __syncthreads();

        uint32_t bufA = sb + (uint32_t)(kt & 1) * STG;
        uint32_t bufB = bufA + A_ST;

        #pragma unroll
        for (int o = 0; o < 3; o++) {
            #pragma unroll
            for (int kk = 0; kk < 2; kk++) {
                uint32_t bh[8][2];
                #pragma unroll
                for (int t = 0; t < 8; t++) {
                    uint32_t base = bufB + o * 8192 + bOff[t];
                    LDSM_X2(bh[t], base + ((uint32_t)((kk * 2 + hiB) ^ bSw[t]) << 4));
                }
                #pragma unroll
                for (int s = 0; s < 2; s++) {
                    uint32_t ah[4];
                    uint32_t base = bufA + o * 8192 + aOff[s];
                    LDSM_X4(ah, base + ((uint32_t)((kk * 2 + hiA) ^ aSw[s]) << 4));
                    #pragma unroll
                    for (int t = 0; t < 8; t++)
                        MMA16816(acc[s][t], ah, bh[t]);
                }
            }
        }
        __syncthreads();
        int j = kt + 2;
        if (j < NK)
            load_stage_kan(A3, B3, N, m0, n0, j, bufA, bufB, tid);
        asm volatile("cp.async.commit_group;" ::: "memory");
    }

    // epilogue
    #pragma unroll
    for (int t = 0; t < 8; t++) {
        int col = n0 + wn * 64 + t * 8 + (lane & 3) * 2;
        float c0a = c0v[col], c0b = c0v[col + 1];
        #pragma unroll
        for (int s = 0; s < 2; s++) {
            int r0 = m0 + wm * 32 + s * 16 + (lane >> 2);
            float2 v0 = make_float2(acc[s][t][0] + c0a, acc[s][t][1] + c0b);
            float2 v1 = make_float2(acc[s][t][2] + c0a, acc[s][t][3] + c0b);
            *reinterpret_cast<float2*>(C + (size_t)r0 * N + col) = v0;
            *reinterpret_cast<float2*>(C + (size_t)(r0 + 8) * N + col) = v1;
        }
    }
}

// ---------------- LayerNorm 2 ----------------
__global__ void ln2_kernel(const float* __restrict__ g, const float* __restrict__ beta) {
    __shared__ float red[256];
    int t = threadIdx.x;
    float* p = g_h2 + (size_t)blockIdx.x * OUTC;
    float v[2];
    float s = 0.f;
    #pragma unroll
    for (int i = 0; i < 2; i++) { v[i] = p[t + i * 256]; s += v[i]; }
    float mu = block_reduce_sum(s, red, t) * (1.f / OUTC);
    float s2 = 0.f;
    #pragma unroll
    for (int i = 0; i < 2; i++) { float d = v[i] - mu; s2 += d * d; }
    float rstd = rsqrtf(block_reduce_sum(s2, red, t) * (1.f / OUTC) + EPS);
    #pragma unroll
    for (int i = 0; i < 2; i++) {
        int o = t + i * 256;
        p[o] = (v[i] - mu) * rstd * g[o] + beta[o];
    }
}

// ---------------- mean over L (two-phase, deterministic) ----------------
__global__ void reduce1_kernel() {
    int b = blockIdx.y, seg = blockIdx.x;
    int o = threadIdx.x;
    const float* p = g_h2 + ((size_t)b * LEN + seg * 64) * OUTC + o;
    float s = 0.f;
    #pragma unroll 8
    for (int l = 0; l < 64; l++) s += p[(size_t)l * OUTC];
    g_part[((size_t)b * 16 + seg) * OUTC + o] = s;
}

__global__ void reduce2_kernel(float* __restrict__ out) {
    int b = blockIdx.x, o = threadIdx.x;
    const float* p = g_part + (size_t)b * 16 * OUTC + o;
    float s = 0.f;
    #pragma unroll
    for (int seg = 0; seg < 16; seg++) s += p[(size_t)seg * OUTC];
    out[b * OUTC + o] = s * (1.f / LEN);
}

// ---------------- launch ----------------
extern "C" void kernel_launch(void* const* d_in, const int* in_sizes, int n_in,
                              void* d_out, int out_size) {
    const float* x       = (const float*)d_in[0];
    const float* W_in    = (const float*)d_in[1];
    const float* b_in    = (const float*)d_in[2];
    const float* coeffs1 = (const float*)d_in[3];
    const float* bias1   = (const float*)d_in[4];
    const float* g1      = (const float*)d_in[5];
    const float* beta1   = (const float*)d_in[6];
    const float* coeffs2 = (const float*)d_in[7];
    const float* bias2   = (const float*)d_in[8];
    const float* g2      = (const float*)d_in[9];
    const float* beta2   = (const float*)d_in[10];
    float* out = (float*)d_out;

    cudaFuncSetAttribute(gemm_kan_mma<1>, cudaFuncAttributeMaxDynamicSharedMemorySize, SMEM_GEMM);
    cudaFuncSetAttribute(gemm_kan_mma<2>, cudaFuncAttributeMaxDynamicSharedMemorySize, SMEM_GEMM);

    repackB_kernel<1><<<HID, 256>>>(coeffs1, bias1);
    repackB_kernel<2><<<OUTC, 256>>>(coeffs2, bias2);

    gemm_proj_kernel<<<dim3(HID / GBN, MTOT / GBM), NTHR>>>(x, W_in, b_in);
    gemm_kan_mma<1><<<dim3(HID / 128, MTOT / 128), 256, SMEM_GEMM>>>();
    ln_gelu_split_kernel<<<MTOT, 256>>>(g1, beta1);
    gemm_kan_mma<2><<<dim3(OUTC / 128, MTOT / 128), 256, SMEM_GEMM>>>();
    ln2_kernel<<<MTOT, 256>>>(g2, beta2);
    reduce1_kernel<<<dim3(16, BATCH), OUTC>>>();
    reduce2_kernel<<<BATCH, OUTC>>>(out);
}